// round 11
// baseline (speedup 1.0000x reference)
#include <cuda_runtime.h>
#include <math.h>

#define BB 20
#define LL 20
#define VV 100000

// per-batch loss scratch + completion counter (device globals — no allocation allowed)
__device__ float    g_loss[BB];
__device__ unsigned g_count = 0;

// Single fused kernel. One block per batch:
//   1) gather P[b,:,:] (400 scattered loads) into smem
//   2) warp 0 runs the anti-diagonal wavefront DP -> g_loss[b]
//   3) threadfence-reduction: last block to finish sums g_loss -> out[0]
__global__ void calcs_fused_kernel(const float* __restrict__ topic_prob,
                                   const int* __restrict__ hard_label,
                                   float* __restrict__ out) {
    __shared__ int   s_lab[LL];
    __shared__ float sP[LL * LL];
    __shared__ int   s_last;

    const int b = blockIdx.x;
    const int t = threadIdx.x;

    if (t < LL) s_lab[t] = hard_label[b * LL + t];
    __syncthreads();

    if (t < LL * LL) {
        int j = t / LL;
        int k = t - j * LL;
        int idx = s_lab[k];
        idx = min(max(idx, 0), VV - 1);              // jnp.clip
        sP[t] = topic_prob[(size_t)b * LL * VV + (size_t)j * VV + (size_t)idx];
    }
    __syncthreads();

    // Warp 0: wavefront DP. Lane k owns dp column k+1.
    // Cell (j+1, k+1) is computed at step = j + k:
    //   up   = dp[j  ][k+1] = my value from step-1            (v1)
    //   left = dp[j+1][k  ] = lane k-1 value from step-1      (shfl_up v1)
    //   diag = dp[j  ][k  ] = lane k-1 value from step-2      (shfl_up v2)
    if (t < 32) {
        const int k = t;
        unsigned mbits = __ballot_sync(0xFFFFFFFFu, (k < LL) && (s_lab[k & (LL-1)] >= 0));
        mbits &= (1u << LL) - 1u;
        const int len = __popc(mbits);

        float v1 = 0.0f, v2 = 0.0f;
        float final_v = 0.0f;

        #pragma unroll
        for (int step = 0; step < 2 * LL - 1; ++step) {
            float left = __shfl_up_sync(0xFFFFFFFFu, v1, 1);
            float diag = __shfl_up_sync(0xFFFFFFFFu, v2, 1);
            if (k == 0) { left = 0.0f; diag = 0.0f; }  // dp row/col 0 are zero
            const float up = v1;

            const int  j      = step - k;
            const bool active = (k < LL) && (j >= 0) && (j < LL);

            float newv1 = v1;
            if (active) {
                float p   = sP[j * LL + k];
                float val = p * (diag + 1.0f) + (1.0f - p) * fmaxf(left, up);
                unsigned ok = ((mbits >> j) & 1u) & ((mbits >> k) & 1u);
                val = ok ? val : 0.0f;
                newv1 = val;
                if ((j + 1 == len) && (k + 1 == len)) final_v = val;  // dp[len][len]
            }
            v2 = v1;
            v1 = newv1;
        }

        const int src = (len > 0) ? (len - 1) : 0;
        const float f = __shfl_sync(0xFFFFFFFFu, final_v, src);
        if (t == 0) {
            g_loss[b] = -logf(f / (float)len);
            __threadfence();                       // publish g_loss[b] to L2
            unsigned prev = atomicAdd(&g_count, 1u);
            s_last = (prev == BB - 1) ? 1 : 0;     // elect the last-finishing block
        }
    }
    __syncthreads();

    // Last block performs the deterministic 20-element reduction.
    if (s_last && t < 32) {
        __threadfence();                           // acquire side of the fence pair
        float v = (t < BB) ? *((volatile float*)&g_loss[t]) : 0.0f;
        #pragma unroll
        for (int off = 16; off > 0; off >>= 1)
            v += __shfl_down_sync(0xFFFFFFFFu, v, off);
        if (t == 0) {
            out[0] = v / (float)BB;
            g_count = 0;                           // reset for the next graph replay
        }
    }
}

extern "C" void kernel_launch(void* const* d_in, const int* in_sizes, int n_in,
                              void* d_out, int out_size) {
    const float* topic_prob = (const float*)d_in[0];
    const int*   hard_label = (const int*)d_in[1];
    float*       out        = (float*)d_out;

    calcs_fused_kernel<<<BB, 512>>>(topic_prob, hard_label, out);
}

// round 13
// speedup vs baseline: 1.0208x; 1.0208x over previous
#include <cuda_runtime.h>
#include <math.h>

#define BB 20
#define LL 20
#define VV 100000

// per-batch loss scratch + completion counter (device globals — no allocation allowed)
__device__ float    g_loss[BB];
__device__ unsigned g_count = 0;

// Single fused kernel. One block per batch:
//   1) gather P[b,:,:] (400 scattered loads) into smem
//   2) warp 0 runs the anti-diagonal wavefront DP -> g_loss[b]
//   3) threadfence-reduction: last block to finish sums g_loss -> out[0]
__global__ void calcs_fused_kernel(const float* __restrict__ topic_prob,
                                   const int* __restrict__ hard_label,
                                   float* __restrict__ out) {
    __shared__ int   s_lab[LL];
    __shared__ float sP[LL * LL];
    __shared__ int   s_last;

    const int b = blockIdx.x;
    const int t = threadIdx.x;

    if (t < LL) s_lab[t] = hard_label[b * LL + t];
    __syncthreads();

    if (t < LL * LL) {
        int j = t / LL;
        int k = t - j * LL;
        int idx = s_lab[k];
        idx = min(max(idx, 0), VV - 1);              // jnp.clip
        sP[t] = topic_prob[(size_t)b * LL * VV + (size_t)j * VV + (size_t)idx];
    }
    __syncthreads();

    // Warp 0: wavefront DP. Lane k owns dp column k+1.
    // Cell (j+1, k+1) is computed at step = j + k:
    //   up   = dp[j  ][k+1] = my value from step-1            (v1)
    //   left = dp[j+1][k  ] = lane k-1 value from step-1      (shfl_up v1)
    //   diag = dp[j  ][k  ] = lane k-1 value from step-2      (shfl_up v2)
    if (t < 32) {
        const int k = t;
        unsigned mbits = __ballot_sync(0xFFFFFFFFu, (k < LL) && (s_lab[k & (LL-1)] >= 0));
        mbits &= (1u << LL) - 1u;
        const int len = __popc(mbits);

        float v1 = 0.0f, v2 = 0.0f;
        float final_v = 0.0f;

        #pragma unroll
        for (int step = 0; step < 2 * LL - 1; ++step) {
            float left = __shfl_up_sync(0xFFFFFFFFu, v1, 1);
            float diag = __shfl_up_sync(0xFFFFFFFFu, v2, 1);
            if (k == 0) { left = 0.0f; diag = 0.0f; }  // dp row/col 0 are zero
            const float up = v1;

            const int  j      = step - k;
            const bool active = (k < LL) && (j >= 0) && (j < LL);

            float newv1 = v1;
            if (active) {
                float p   = sP[j * LL + k];
                float val = p * (diag + 1.0f) + (1.0f - p) * fmaxf(left, up);
                unsigned ok = ((mbits >> j) & 1u) & ((mbits >> k) & 1u);
                val = ok ? val : 0.0f;
                newv1 = val;
                if ((j + 1 == len) && (k + 1 == len)) final_v = val;  // dp[len][len]
            }
            v2 = v1;
            v1 = newv1;
        }

        const int src = (len > 0) ? (len - 1) : 0;
        const float f = __shfl_sync(0xFFFFFFFFu, final_v, src);
        if (t == 0) {
            g_loss[b] = -logf(f / (float)len);
            __threadfence();                       // publish g_loss[b] to L2
            unsigned prev = atomicAdd(&g_count, 1u);
            s_last = (prev == BB - 1) ? 1 : 0;     // elect the last-finishing block
        }
    }
    __syncthreads();

    // Last block performs the deterministic 20-element reduction.
    if (s_last && t < 32) {
        __threadfence();                           // acquire side of the fence pair
        float v = (t < BB) ? *((volatile float*)&g_loss[t]) : 0.0f;
        #pragma unroll
        for (int off = 16; off > 0; off >>= 1)
            v += __shfl_down_sync(0xFFFFFFFFu, v, off);
        if (t == 0) {
            out[0] = v / (float)BB;
            g_count = 0;                           // reset for the next graph replay
        }
    }
}

extern "C" void kernel_launch(void* const* d_in, const int* in_sizes, int n_in,
                              void* d_out, int out_size) {
    const float* topic_prob = (const float*)d_in[0];
    const int*   hard_label = (const int*)d_in[1];
    float*       out        = (float*)d_out;

    calcs_fused_kernel<<<BB, 512>>>(topic_prob, hard_label, out);
}